// round 7
// baseline (speedup 1.0000x reference)
#include <cuda_runtime.h>
#include <math.h>

#define BATCH 8
#define NQ    300
#define CH    256
#define NLVL  4
#define P_IN  32
#define NQTOT (BATCH * NQ)

// per-query params: sx, sy, zw0..zw3, pad, pad  (8 floats)
__device__ float g_params[NQTOT * 8];

// ---------------- Kernel A: warp-per-query projection + coords ----------------
__global__ __launch_bounds__(256)
void prep_kernel(const float* __restrict__ qpos,
                 const float* __restrict__ qcont,
                 const float* __restrict__ Woff,
                 const float* __restrict__ boff,
                 const float* __restrict__ sigma_z)
{
    const int warp = (blockIdx.x * blockDim.x + threadIdx.x) >> 5;
    if (warp >= NQTOT) return;
    const int lane = threadIdx.x & 31;

    // each lane handles 8 consecutive channels
    const float4* q4 = (const float4*)(qcont + (size_t)warp * CH) + lane * 2;
    float p0 = 0.f, p1 = 0.f, p2 = 0.f;
#pragma unroll
    for (int j = 0; j < 2; j++) {
        const float4 q = q4[j];
        const int c = lane * 8 + j * 4;
        p0 += q.x * Woff[(c+0)*3+0] + q.y * Woff[(c+1)*3+0]
            + q.z * Woff[(c+2)*3+0] + q.w * Woff[(c+3)*3+0];
        p1 += q.x * Woff[(c+0)*3+1] + q.y * Woff[(c+1)*3+1]
            + q.z * Woff[(c+2)*3+1] + q.w * Woff[(c+3)*3+1];
        p2 += q.x * Woff[(c+0)*3+2] + q.y * Woff[(c+1)*3+2]
            + q.z * Woff[(c+2)*3+2] + q.w * Woff[(c+3)*3+2];
    }
#pragma unroll
    for (int o = 16; o > 0; o >>= 1) {
        p0 += __shfl_xor_sync(0xffffffffu, p0, o);
        p1 += __shfl_xor_sync(0xffffffffu, p1, o);
        p2 += __shfl_xor_sync(0xffffffffu, p2, o);
    }
    if (lane == 0) {
        const float dx = p0 + boff[0];
        const float dy = p1 + boff[1];
        const float dz = p2 + boff[2];
        const float x = qpos[warp*4+0], y = qpos[warp*4+1];
        const float z = qpos[warp*4+2], r = qpos[warp*4+3];
        const float sx = x + dx * exp2f(z - r);
        const float sy = y + dy * exp2f(z + r);
        const float sz = z + dz;
        const float sig = sigma_z[0];
        const float invs = 1.0f / (2.0f * sig * sig);

        float g[NLVL], m = -1e30f;
#pragma unroll
        for (int l = 0; l < NLVL; l++) {
            const float d = sz - (float)l;
            g[l] = expf(-d * d * invs);
            m = fmaxf(m, g[l]);
        }
        float e[NLVL], se = 0.f;
#pragma unroll
        for (int l = 0; l < NLVL; l++) { e[l] = expf(g[l] - m); se += e[l]; }
        const float invse = 1.0f / se;

        float* p = g_params + warp * 8;
        p[0] = sx; p[1] = sy;
#pragma unroll
        for (int l = 0; l < NLVL; l++) p[2 + l] = e[l] * invse;
    }
}

// ---------------- Kernel B: gather + broadcast store ----------------
__global__ __launch_bounds__(CH, 8)
void gather_kernel(const float* __restrict__ f0,
                   const float* __restrict__ f1,
                   const float* __restrict__ f2,
                   const float* __restrict__ f3,
                   float* __restrict__ out)
{
    const int idx = blockIdx.x;        // b*NQ + n
    const int t   = threadIdx.x;
    const int b   = idx / NQ;

    __shared__ __align__(16) float s_acc[CH];

    const float* prm = g_params + idx * 8;
    const float sx = prm[0], sy = prm[1];
    float zw[NLVL];
#pragma unroll
    for (int l = 0; l < NLVL; l++) zw[l] = prm[2 + l];

    const float* fptr[NLVL] = { f0, f1, f2, f3 };
    const int    HS[NLVL]   = { 100, 50, 25, 13 };

    const int corner = t & 3;          // 0:(y0,x0) 1:(y0,x1) 2:(y1,x0) 3:(y1,x1)
    const int cg     = t >> 2;         // channel group 0..63

    float acc0 = 0.f, acc1 = 0.f, acc2 = 0.f, acc3 = 0.f;
#pragma unroll
    for (int l = 0; l < NLVL; l++) {
        const int   H  = HS[l];
        const int   HH = H * H;
        const float fH = (float)H;
        const float px = fminf(fmaxf(sx - 0.5f, 0.0f), fH - 1.0f);
        const float py = fminf(fmaxf(sy - 0.5f, 0.0f), fH - 1.0f);
        const float x0f = floorf(px), y0f = floorf(py);
        const float wx = px - x0f, wy = py - y0f;
        const int x0 = (int)x0f, y0 = (int)y0f;
        const int x1 = min(x0 + 1, H - 1);
        const int y1 = min(y0 + 1, H - 1);

        const int   xsel = (corner & 1) ? x1 : x0;
        const int   ysel = (corner & 2) ? y1 : y0;
        const float wsel = ((corner & 1) ? wx : 1.0f - wx)
                         * ((corner & 2) ? wy : 1.0f - wy) * zw[l];

        const float* base = fptr[l] + (size_t)b * CH * HH + ysel * H + xsel;
        acc0 += wsel * __ldg(base + (size_t)(cg      ) * HH);
        acc1 += wsel * __ldg(base + (size_t)(cg +  64) * HH);
        acc2 += wsel * __ldg(base + (size_t)(cg + 128) * HH);
        acc3 += wsel * __ldg(base + (size_t)(cg + 192) * HH);
    }

    // quad butterfly over the 4 corners
    acc0 += __shfl_xor_sync(0xffffffffu, acc0, 1);
    acc0 += __shfl_xor_sync(0xffffffffu, acc0, 2);
    acc1 += __shfl_xor_sync(0xffffffffu, acc1, 1);
    acc1 += __shfl_xor_sync(0xffffffffu, acc1, 2);
    acc2 += __shfl_xor_sync(0xffffffffu, acc2, 1);
    acc2 += __shfl_xor_sync(0xffffffffu, acc2, 2);
    acc3 += __shfl_xor_sync(0xffffffffu, acc3, 1);
    acc3 += __shfl_xor_sync(0xffffffffu, acc3, 2);

    if (corner == 0) {
        s_acc[cg      ] = acc0;
        s_acc[cg +  64] = acc1;
        s_acc[cg + 128] = acc2;
        s_acc[cg + 192] = acc3;
    }
    __syncthreads();

    // broadcast to P_IN points, evict-first streaming stores
    const float4 v = ((const float4*)s_acc)[t & 63];
    float4* ov = (float4*)out + (size_t)idx * (P_IN * CH / 4);
#pragma unroll
    for (int i = 0; i < 8; i++)
        __stcs(&ov[t + i * CH], v);
}

extern "C" void kernel_launch(void* const* d_in, const int* in_sizes, int n_in,
                              void* d_out, int out_size)
{
    const float* f0    = (const float*)d_in[0];
    const float* f1    = (const float*)d_in[1];
    const float* f2    = (const float*)d_in[2];
    const float* f3    = (const float*)d_in[3];
    const float* qpos  = (const float*)d_in[4];
    const float* qcont = (const float*)d_in[5];
    const float* Woff  = (const float*)d_in[6];
    const float* boff  = (const float*)d_in[7];
    const float* sigz  = (const float*)d_in[8];
    float* out = (float*)d_out;

    // A: 2400 warps -> 300 CTAs of 256
    prep_kernel<<<(NQTOT * 32 + 255) / 256, 256>>>(qpos, qcont, Woff, boff, sigz);
    // B: one CTA per query
    gather_kernel<<<NQTOT, CH>>>(f0, f1, f2, f3, out);
}